// round 2
// baseline (speedup 1.0000x reference)
#include <cuda_runtime.h>

#define B_   64
#define S_   200
#define DK_  32
#define NQ1  4097

// Persistent device state (no allocations allowed in kernel_launch).
static __device__ float g_h[B_ * NQ1 * DK_];       // h state  (33.6 MB)
static __device__ float g_ht[S_ * B_ * DK_];       // h_tilde per step
static __device__ float g_learn[S_ * B_ * DK_];    // all_learning [t][b][k]
static __device__ float g_it[S_ * B_ * DK_];       // it_emb      [t][b][k]

typedef unsigned long long ull;

__device__ __forceinline__ ull ffma2(ull a, ull b, ull c) {
    ull d;
    asm("fma.rn.f32x2 %0, %1, %2, %3;" : "=l"(d) : "l"(a), "l"(b), "l"(c));
    return d;
}
__device__ __forceinline__ ull fadd2(ull a, ull b) {
    ull d;
    asm("add.rn.f32x2 %0, %1, %2;" : "=l"(d) : "l"(a), "l"(b));
    return d;
}
__device__ __forceinline__ void upk2(ull v, float& lo, float& hi) {
    asm("mov.b64 {%0,%1}, %2;" : "=f"(lo), "=f"(hi) : "l"(v));
}

// ---------------------------------------------------------------------------
// K1: init h state (broadcast h0 over batch), zero h_tilde buffers, pred[:,0]=0
// ---------------------------------------------------------------------------
__global__ void k_init(const float* __restrict__ h0, float* __restrict__ pred) {
    int stride = gridDim.x * blockDim.x;
    int gid = blockIdx.x * blockDim.x + threadIdx.x;
    for (int i = gid; i < B_ * NQ1 * DK_; i += stride) {
        int nk = i % (NQ1 * DK_);
        g_h[i] = h0[nk];
    }
    for (int i = gid; i < S_ * B_ * DK_; i += stride) {
        g_ht[i] = 0.0f;
    }
    if (gid < B_) pred[gid * S_] = 0.0f;
}

// ---------------------------------------------------------------------------
// K2: precompute all_learning[t][b][k] and it_emb[t][b][k] for all t
// ---------------------------------------------------------------------------
__global__ void k_embed(const int* __restrict__ e_data, const int* __restrict__ at_data,
                        const int* __restrict__ it_data, const float* __restrict__ a_data,
                        const float* __restrict__ E_e, const float* __restrict__ E_at,
                        const float* __restrict__ E_it,
                        const float* __restrict__ W1, const float* __restrict__ b1) {
    int idx = blockIdx.x * blockDim.x + threadIdx.x;
    if (idx >= S_ * B_ * DK_) return;
    int t = idx / (B_ * DK_);
    int rem = idx - t * (B_ * DK_);
    int b = rem >> 5;
    int k = rem & 31;

    int e  = e_data[b * S_ + t];
    int at = at_data[b * S_ + t];
    int it = it_data[b * S_ + t];
    float a = a_data[b * S_ + t];

    const float* ee  = E_e  + e  * DK_;
    const float* eat = E_at + at * DK_;
    const float* w1k = W1 + k * (3 * DK_);

    float s = b1[k];
    float ws = 0.0f;
#pragma unroll
    for (int j = 0; j < DK_; j++) {
        s = fmaf(ee[j],  w1k[j],        s);
        s = fmaf(eat[j], w1k[DK_ + j],  s);
        ws += w1k[2 * DK_ + j];
    }
    s = fmaf(a, ws, s);

    g_learn[(t * B_ + b) * DK_ + k] = s;
    g_it[(t * B_ + b) * DK_ + k]    = E_it[it * DK_ + k];
}

// ---------------------------------------------------------------------------
// K3: h_tilde0[b] = sum_n q[e_data[b,0], n] * h0[n,:]
// ---------------------------------------------------------------------------
__global__ void k_ht0(const int* __restrict__ e_data, const float* __restrict__ q,
                      const float* __restrict__ h0) {
    int b = blockIdx.x;
    int w = threadIdx.x >> 5;
    int lane = threadIdx.x & 31;
    const float* qr = q + (long)e_data[b * S_] * NQ1;
    float acc = 0.0f;
    for (int n = w; n < NQ1; n += 8) {
        float qv = qr[n];
        if (qv != 0.0f) acc = fmaf(qv, h0[n * DK_ + lane], acc);
    }
    atomicAdd(&g_ht[b * DK_ + lane], acc);
}

// ---------------------------------------------------------------------------
// Kstep(t): one RNN step. grid = (17, 64), 256 threads.
//   block prologue (warp0): LG[b], c[b]   (warp1, bx==0): y_{t-1} -> pred[b][t]
//   main loop: each warp owns a 32-row tile; lane k = output dim k.
// ---------------------------------------------------------------------------
__global__ void __launch_bounds__(256)
k_step(int t, const int* __restrict__ e_data, const float* __restrict__ q,
       const float* __restrict__ E_e,
       const float* __restrict__ W2, const float* __restrict__ b2,
       const float* __restrict__ W3, const float* __restrict__ b3,
       const float* __restrict__ W4, const float* __restrict__ b4,
       const float* __restrict__ W5, const float* __restrict__ b5,
       float* __restrict__ pred) {
    __shared__ float sh_x[4 * DK_];
    __shared__ float sh_LG[DK_];
    __shared__ float sh_c[DK_];

    const int b = blockIdx.y;
    const int tid = threadIdx.x;
    const int w = tid >> 5;
    const int lane = tid & 31;

    // Each lane holds W4h[lane, 0..31] as 16 f32x2 registers (amortized over all rows).
    ull w2r[16];
    {
        const ulonglong2* wp = reinterpret_cast<const ulonglong2*>(W4 + lane * (3 * DK_));
#pragma unroll
        for (int i = 0; i < 8; i++) {
            ulonglong2 p = wp[i];
            w2r[2 * i] = p.x;
            w2r[2 * i + 1] = p.y;
        }
    }

    // Stage x = [learning_pre, it, learning, h_tilde_pre]
    if (tid < 128) {
        int j = tid;
        float v;
        if (j < 32)       v = (t == 0) ? 0.0f : g_learn[((t - 1) * B_ + b) * DK_ + j];
        else if (j < 64)  v = g_it[(t * B_ + b) * DK_ + (j - 32)];
        else if (j < 96)  v = g_learn[(t * B_ + b) * DK_ + (j - 64)];
        else              v = g_ht[(t * B_ + b) * DK_ + (j - 96)];
        sh_x[j] = v;
    }
    __syncthreads();

    if (w == 0) {
        int k = lane;
        const float* w2k = W2 + k * 128;
        const float* w3k = W3 + k * 128;
        float lg = b2[k];
        float gl = b3[k];
#pragma unroll 16
        for (int j = 0; j < 128; j++) {
            float xv = sh_x[j];
            lg = fmaf(xv, w2k[j], lg);
            gl = fmaf(xv, w3k[j], gl);
        }
        lg = tanhf(lg);
        gl = 1.0f / (1.0f + expf(-gl));
        float LG = gl * (lg + 1.0f) * 0.5f;
        sh_LG[k] = LG;
        __syncwarp();
        const float* w4k = W4 + k * (3 * DK_);
        float c = b4[k];
#pragma unroll
        for (int j = 0; j < DK_; j++) {
            c = fmaf(sh_LG[j], w4k[DK_ + j], c);
            c = fmaf(sh_x[DK_ + j], w4k[2 * DK_ + j], c);
        }
        sh_c[k] = c;
    } else if (w == 1 && blockIdx.x == 0 && t > 0) {
        // y_{t-1}: uses ht_buf[t] (completed last step) and E_e[e_data[:, t]]
        int k = lane;
        int en = e_data[b * S_ + t];
        const float* ee = E_e + en * DK_;
        const float* ht = g_ht + (t * B_ + b) * DK_;
        const float* w5k = W5 + k * (2 * DK_);
        float z = b5[k];
#pragma unroll
        for (int j = 0; j < DK_; j++) {
            z = fmaf(ee[j], w5k[j], z);
            z = fmaf(ht[j], w5k[DK_ + j], z);
        }
        float s = 1.0f / (1.0f + expf(-z));
#pragma unroll
        for (int off = 16; off; off >>= 1)
            s += __shfl_xor_sync(0xffffffffu, s, off);
        if (lane == 0) pred[b * S_ + t] = s * (1.0f / DK_);
    }
    __syncthreads();

    const float LGk = sh_LG[lane];
    const float ck = sh_c[lane];
    const int e_t = e_data[b * S_ + t];
    const int e_n = e_data[b * S_ + t + 1];
    const float* qe_row = q + (long)e_t * NQ1;
    const float* qn_row = q + (long)e_n * NQ1;
    float* htn = g_ht + ((t + 1) * B_ + b) * DK_;

    const int base = (blockIdx.x * 8 + w) * 32;
    for (int r = 0; r < 32; ++r) {
        const int row = base + r;
        if (row >= NQ1) break;
        const int hb = (b * NQ1 + row) * DK_;
        const ulonglong2* hp = reinterpret_cast<const ulonglong2*>(g_h + hb);

        ull a0 = 0ull, a1 = 0ull, a2 = 0ull, a3 = 0ull;
#pragma unroll
        for (int i = 0; i < 4; i++) {
            ulonglong2 p0 = hp[2 * i];
            ulonglong2 p1 = hp[2 * i + 1];
            a0 = ffma2(p0.x, w2r[4 * i + 0], a0);
            a1 = ffma2(p0.y, w2r[4 * i + 1], a1);
            a2 = ffma2(p1.x, w2r[4 * i + 2], a2);
            a3 = ffma2(p1.y, w2r[4 * i + 3], a3);
        }
        ull ssum = fadd2(fadd2(a0, a1), fadd2(a2, a3));
        float lo, hi;
        upk2(ssum, lo, hi);
        float z = lo + hi + ck;

        float ex = __expf(-z);
        float gm = __fdividef(1.0f, 1.0f + ex);

        float hk = g_h[hb + lane];
        float qe = __ldg(qe_row + row);
        float qn = __ldg(qn_row + row);
        float hn = fmaf(gm, hk, qe * LGk);
        g_h[hb + lane] = hn;
        if (qn != 0.0f) atomicAdd(htn + lane, qn * hn);
    }
}

// ---------------------------------------------------------------------------
// Kfinal: y_{S-2} -> pred[:, S-1]
// ---------------------------------------------------------------------------
__global__ void k_final(const int* __restrict__ e_data, const float* __restrict__ E_e,
                        const float* __restrict__ W5, const float* __restrict__ b5,
                        float* __restrict__ pred) {
    int b = blockIdx.x;
    int k = threadIdx.x;
    int tlast = S_ - 1;
    int en = e_data[b * S_ + tlast];
    const float* ee = E_e + en * DK_;
    const float* ht = g_ht + (tlast * B_ + b) * DK_;
    const float* w5k = W5 + k * (2 * DK_);
    float z = b5[k];
#pragma unroll
    for (int j = 0; j < DK_; j++) {
        z = fmaf(ee[j], w5k[j], z);
        z = fmaf(ht[j], w5k[DK_ + j], z);
    }
    float s = 1.0f / (1.0f + expf(-z));
#pragma unroll
    for (int off = 16; off; off >>= 1)
        s += __shfl_xor_sync(0xffffffffu, s, off);
    if (k == 0) pred[b * S_ + tlast] = s * (1.0f / DK_);
}

// ---------------------------------------------------------------------------
extern "C" void kernel_launch(void* const* d_in, const int* in_sizes, int n_in,
                              void* d_out, int out_size) {
    const int*   e_data  = (const int*)d_in[0];
    const int*   at_data = (const int*)d_in[1];
    const int*   it_data = (const int*)d_in[2];
    const float* a_data  = (const float*)d_in[3];
    const float* q       = (const float*)d_in[4];
    const float* E_e     = (const float*)d_in[5];
    const float* E_at    = (const float*)d_in[6];
    const float* E_it    = (const float*)d_in[7];
    const float* W1      = (const float*)d_in[8];
    const float* b1      = (const float*)d_in[9];
    const float* W2      = (const float*)d_in[10];
    const float* b2      = (const float*)d_in[11];
    const float* W3      = (const float*)d_in[12];
    const float* b3      = (const float*)d_in[13];
    const float* W4      = (const float*)d_in[14];
    const float* b4      = (const float*)d_in[15];
    const float* W5      = (const float*)d_in[16];
    const float* b5      = (const float*)d_in[17];
    const float* h0      = (const float*)d_in[18];
    float* pred = (float*)d_out;

    k_init<<<2048, 256>>>(h0, pred);
    k_embed<<<(S_ * B_ * DK_ + 255) / 256, 256>>>(e_data, at_data, it_data, a_data,
                                                  E_e, E_at, E_it, W1, b1);
    k_ht0<<<B_, 256>>>(e_data, q, h0);

    for (int t = 0; t < S_ - 1; t++) {
        k_step<<<dim3(17, B_), 256>>>(t, e_data, q, E_e,
                                      W2, b2, W3, b3, W4, b4, W5, b5, pred);
    }
    k_final<<<B_, 32>>>(e_data, E_e, W5, b5, pred);
}